// round 16
// baseline (speedup 1.0000x reference)
#include <cuda_runtime.h>
#include <cuda_fp16.h>
#include <stdint.h>
#include <math.h>

#define SEQ 2048
#define HIDDEN 2048
#define INTER 4096
#define NH 64
#define DH 64
#define DS 128
#define CHUNK 256
#define NCH 8
#define CONV_DIM 4352
#define PROJ_DIM 8512

// -------- scratch (device globals; no allocation allowed) --------
__device__ float g_proj[SEQ * PROJ_DIM];
__device__ float g_conv[SEQ * CONV_DIM];
__device__ float g_dt[SEQ * NH];
__device__ float g_acum[SEQ * NH];
__device__ float g_cb[NCH * CHUNK * CHUNK];
__device__ float g_states[NCH * NH * DH * DS];
__device__ float g_prev[NCH * NH * DH * DS];
__device__ float g_y[SEQ * INTER];

// fp16 operands for tensor-core GEMMs (single product: hi only)
__device__ __half g_xh[SEQ * HIDDEN];
__device__ __half g_wih[PROJ_DIM * HIDDEN];
__device__ __half g_yh[SEQ * INTER];
__device__ __half g_woh[HIDDEN * INTER];

// ======================= helpers =======================
__device__ __forceinline__ uint32_t smem_u32(const void* p) {
    uint32_t a;
    asm("{ .reg .u64 t; cvta.to.shared.u64 t, %1; cvt.u32.u64 %0, t; }" : "=r"(a) : "l"(p));
    return a;
}

#define LDSM4(r, a) \
    asm volatile("ldmatrix.sync.aligned.m8n8.x4.shared.b16 {%0,%1,%2,%3}, [%4];" \
        : "=r"((r)[0]), "=r"((r)[1]), "=r"((r)[2]), "=r"((r)[3]) : "r"(a))

#define MMA16816(c, a, b0, b1) \
    asm volatile("mma.sync.aligned.m16n8k16.row.col.f32.f16.f16.f32 " \
        "{%0,%1,%2,%3}, {%4,%5,%6,%7}, {%8,%9}, {%0,%1,%2,%3};" \
        : "+f"((c)[0]), "+f"((c)[1]), "+f"((c)[2]), "+f"((c)[3]) \
        : "r"((a)[0]), "r"((a)[1]), "r"((a)[2]), "r"((a)[3]), "r"(b0), "r"(b1))

__device__ __forceinline__ void cp16(uint32_t dst, const void* src) {
    unsigned long long g = (unsigned long long)__cvta_generic_to_global(src);
    asm volatile("cp.async.cg.shared.global [%0], [%1], 16;" :: "r"(dst), "l"(g));
}

// ======================= fp32 -> fp16 =======================
__global__ void split1_kernel(const float* __restrict__ in, __half* __restrict__ hi, int n) {
    int i = (blockIdx.x * blockDim.x + threadIdx.x) * 4;
    if (i >= n) return;
    float4 v = *(const float4*)(in + i);
    *(__half2*)(hi + i)     = __half2(__float2half_rn(v.x), __float2half_rn(v.y));
    *(__half2*)(hi + i + 2) = __half2(__float2half_rn(v.z), __float2half_rn(v.w));
}

// ======================= mma.sync GEMM: C[M, slice] = A[M,K] * B[N,K]^T =======================
// Single fp16 product. CTA 128 x NT, 256 threads (8 warps).
// NT=256: warps 2x4, warp tile 64x64 (0.0625 B/MAC -> MMA-bound).
// NT=64 (tail): warps 8x1, warp tile 16x64.
// 4-stage cp.async, smem pitch 40 half (80B) -> conflict-free ldmatrix.
#define PITCH 40

template<int K, int NT>
__device__ __forceinline__ void issue_tile(uint32_t st, int t, int bm, int bn,
        const __half* __restrict__ Ah, const __half* __restrict__ Bh, int tid) {
    constexpr int ABYTES = 128 * PITCH * 2;
    const int kt = t * 32;
    // A: 128 rows x 4 chunks = 512 chunks, 2 per thread
#pragma unroll
    for (int i = 0; i < 2; i++) {
        int cid = tid + i * 256;
        int r = cid >> 2, q = cid & 3;
        size_t src = (size_t)(bm + r) * K + kt + q * 8;
        cp16(st + (uint32_t)(r * PITCH + q * 8) * 2, Ah + src);
    }
    constexpr int BCH = NT * 4;
#pragma unroll
    for (int i = 0; i < BCH / 256; i++) {
        int cid = tid + i * 256;
        int r = cid >> 2, q = cid & 3;
        size_t src = (size_t)(bn + r) * K + kt + q * 8;
        cp16(st + ABYTES + (uint32_t)(r * PITCH + q * 8) * 2, Bh + src);
    }
}

template<int K, int NS, int NT>
__global__ __launch_bounds__(256, 1) void gemm_mma_kernel(
        const __half* __restrict__ Ah, const __half* __restrict__ Bh,
        float* __restrict__ C, int n0) {
    extern __shared__ char smem[];
    constexpr int ABYTES = 128 * PITCH * 2;
    constexpr int BBYTES = NT * PITCH * 2;
    constexpr int STAGE = ABYTES + BBYTES;
    constexpr int T = K / 32;
    constexpr int WN = (NT == 256) ? 4 : 1;   // warps along n
    constexpr int WM = 8 / WN;                // warps along m
    constexpr int MROWS = 128 / WM;           // rows per warp
    constexpr int NCOLS = NT / WN;            // cols per warp (64)
    constexpr int FM = MROWS / 16;
    constexpr int FN = NCOLS / 8;             // 8

    const int tid = threadIdx.x;
    const int lane = tid & 31, wid = tid >> 5;
    const int wm = wid & (WM - 1), wn = wid / WM;
    const int bm = blockIdx.y * 128;
    const int bn = n0 + blockIdx.x * NT;
    const uint32_t sb = smem_u32(smem);

    float acc[FM][FN][4];
#pragma unroll
    for (int i = 0; i < FM; i++)
#pragma unroll
        for (int j = 0; j < FN; j++)
#pragma unroll
            for (int q = 0; q < 4; q++) acc[i][j][q] = 0.f;

    issue_tile<K, NT>(sb,             0, bm, bn, Ah, Bh, tid);
    asm volatile("cp.async.commit_group;" ::: "memory");
    issue_tile<K, NT>(sb + STAGE,     1, bm, bn, Ah, Bh, tid);
    asm volatile("cp.async.commit_group;" ::: "memory");
    issue_tile<K, NT>(sb + 2 * STAGE, 2, bm, bn, Ah, Bh, tid);
    asm volatile("cp.async.commit_group;" ::: "memory");

    const int lrow = lane & 15;
    const int lcol = (lane >> 4) * 8;
    const uint32_t aoff = (uint32_t)((wm * MROWS + lrow) * PITCH + lcol) * 2;
    const uint32_t boff = ABYTES + (uint32_t)((wn * NCOLS + lrow) * PITCH + lcol) * 2;

    for (int t = 0; t < T; t++) {
        asm volatile("cp.async.wait_group 2;" ::: "memory");
        __syncthreads();
        const uint32_t stg = sb + (uint32_t)(t & 3) * STAGE;
#pragma unroll
        for (int kk = 0; kk < 32; kk += 16) {
            uint32_t ah[FM][4];
#pragma unroll
            for (int fm = 0; fm < FM; fm++)
                LDSM4(ah[fm], stg + aoff + (uint32_t)(fm * 16 * PITCH + kk) * 2);
#pragma unroll
            for (int g = 0; g < FN / 2; g++) {
                uint32_t bd = stg + boff + (uint32_t)(g * 16 * PITCH + kk) * 2;
                uint32_t rh[4];
                LDSM4(rh, bd);
#pragma unroll
                for (int fm = 0; fm < FM; fm++) {
                    MMA16816(acc[fm][2 * g],     ah[fm], rh[0], rh[2]);
                    MMA16816(acc[fm][2 * g + 1], ah[fm], rh[1], rh[3]);
                }
            }
        }
        if (t + 3 < T)
            issue_tile<K, NT>(sb + (uint32_t)((t + 3) & 3) * STAGE, t + 3, bm, bn, Ah, Bh, tid);
        asm volatile("cp.async.commit_group;" ::: "memory");
    }

    const int crow = lane >> 2, ccol = (lane & 3) * 2;
#pragma unroll
    for (int fm = 0; fm < FM; fm++)
#pragma unroll
        for (int fn = 0; fn < FN; fn++) {
            int m = bm + wm * MROWS + fm * 16 + crow;
            int n = bn + wn * NCOLS + fn * 8 + ccol;
            *(float2*)&C[(size_t)m * NS + n]       = make_float2(acc[fm][fn][0], acc[fm][fn][1]);
            *(float2*)&C[(size_t)(m + 8) * NS + n] = make_float2(acc[fm][fn][2], acc[fm][fn][3]);
        }
}

// ======================= depthwise causal conv (K=4) + SiLU =======================
__global__ void conv_silu_kernel(const float* __restrict__ conv_w,
                                 const float* __restrict__ conv_b) {
    int idx = blockIdx.x * blockDim.x + threadIdx.x;
    if (idx >= SEQ * CONV_DIM) return;
    int s = idx / CONV_DIM;
    int c = idx - s * CONV_DIM;
    float w0 = conv_w[c * 4 + 0], w1 = conv_w[c * 4 + 1];
    float w2 = conv_w[c * 4 + 2], w3 = conv_w[c * 4 + 3];
    const float* col = g_proj + INTER + c;
    float acc = conv_b[c];
    if (s >= 3) acc = fmaf(col[(size_t)(s - 3) * PROJ_DIM], w0, acc);
    if (s >= 2) acc = fmaf(col[(size_t)(s - 2) * PROJ_DIM], w1, acc);
    if (s >= 1) acc = fmaf(col[(size_t)(s - 1) * PROJ_DIM], w2, acc);
    acc = fmaf(col[(size_t)s * PROJ_DIM], w3, acc);
    float sig = 1.f / (1.f + __expf(-acc));
    g_conv[idx] = acc * sig;
}

// ======================= dt = softplus(dt_raw + dt_bias) =======================
__global__ void dt_kernel(const float* __restrict__ dt_bias) {
    int idx = blockIdx.x * blockDim.x + threadIdx.x;
    int h = idx & 63;
    int s = idx >> 6;
    float v = g_proj[(size_t)s * PROJ_DIM + (INTER + CONV_DIM) + h] + dt_bias[h];
    g_dt[idx] = (v > 20.f) ? v : log1pf(__expf(v));
}

// ======================= per-chunk cumsum(dt*A): warp scan per (c,h) =======================
__global__ void acum_kernel(const float* __restrict__ A_log) {
    int wg = blockIdx.x * 8 + (threadIdx.x >> 5);
    int lane = threadIdx.x & 31;
    int c = wg >> 6, h = wg & 63;
    float A = -__expf(A_log[h]);
    const float* dtp = g_dt + ((size_t)c * CHUNK) * NH + h;
    float v[8];
    float run = 0.f;
#pragma unroll
    for (int j = 0; j < 8; j++) {
        v[j] = dtp[(size_t)(lane * 8 + j) * NH] * A;
        run += v[j];
    }
    float s = run;
#pragma unroll
    for (int o = 1; o < 32; o <<= 1) {
        float t = __shfl_up_sync(0xffffffffu, s, o);
        if (lane >= o) s += t;
    }
    float acc = s - run;
    float* acp = g_acum + ((size_t)c * CHUNK) * NH + h;
#pragma unroll
    for (int j = 0; j < 8; j++) {
        acc += v[j];
        acp[(size_t)(lane * 8 + j) * NH] = acc;
    }
}

// ======================= CB[c][t][s] = C_t . B_s (shared over heads), s<=t tiles only =======================
__global__ __launch_bounds__(256) void cb_kernel() {
    int st = blockIdx.x, tt = blockIdx.y, c = blockIdx.z;
    if (st > tt) return;
    __shared__ float Cs[32][68];
    __shared__ float Bs2[32][68];
    const int tid = threadIdx.x;
    const int tx = tid & 15, ty = tid >> 4;
    float acc[4][4] = {};
    for (int n0 = 0; n0 < DS; n0 += 32) {
        __syncthreads();
        for (int e = tid; e < 64 * 32; e += 256) {
            int r = e >> 5, kk = e & 31;
            Cs[kk][r]  = g_conv[(size_t)(c * CHUNK + tt * 64 + r) * CONV_DIM + INTER + DS + n0 + kk];
            Bs2[kk][r] = g_conv[(size_t)(c * CHUNK + st * 64 + r) * CONV_DIM + INTER + n0 + kk];
        }
        __syncthreads();
#pragma unroll
        for (int k = 0; k < 32; k++) {
            float4 a = *(const float4*)&Cs[k][ty * 4];
            float4 b = *(const float4*)&Bs2[k][tx * 4];
            float av[4] = {a.x, a.y, a.z, a.w};
            float bv[4] = {b.x, b.y, b.z, b.w};
#pragma unroll
            for (int i = 0; i < 4; i++)
#pragma unroll
                for (int j = 0; j < 4; j++)
                    acc[i][j] = fmaf(av[i], bv[j], acc[i][j]);
        }
    }
#pragma unroll
    for (int i = 0; i < 4; i++)
        *(float4*)&g_cb[(size_t)c * CHUNK * CHUNK + (size_t)(tt * 64 + ty * 4 + i) * CHUNK + st * 64 + tx * 4] =
            make_float4(acc[i][0], acc[i][1], acc[i][2], acc[i][3]);
}

// ======================= chunk end states: states[c][h][p][n] =======================
__global__ __launch_bounds__(256) void states_kernel() {
    int h = blockIdx.x, c = blockIdx.y;
    __shared__ float Bt[32][DS];
    __shared__ float Xt[32][DH];
    __shared__ float wv[32];
    const int tid = threadIdx.x;
    const int p = tid >> 2, ng = tid & 3;
    float acc[32];
#pragma unroll
    for (int j = 0; j < 32; j++) acc[j] = 0.f;
    float Aend = g_acum[(size_t)(c * CHUNK + CHUNK - 1) * NH + h];
    for (int lt = 0; lt < 8; lt++) {
        __syncthreads();
        for (int e = tid; e < 32 * DS; e += 256) {
            int r = e >> 7, n = e & 127;
            Bt[r][n] = g_conv[(size_t)(c * CHUNK + lt * 32 + r) * CONV_DIM + INTER + n];
        }
        for (int e = tid; e < 32 * DH; e += 256) {
            int r = e >> 6, pp = e & 63;
            Xt[r][pp] = g_conv[(size_t)(c * CHUNK + lt * 32 + r) * CONV_DIM + h * DH + pp];
        }
        if (tid < 32) {
            int l = lt * 32 + tid;
            float ac = g_acum[(size_t)(c * CHUNK + l) * NH + h];
            wv[tid] = __expf(Aend - ac) * g_dt[(size_t)(c * CHUNK + l) * NH + h];
        }
        __syncthreads();
#pragma unroll 4
        for (int ls = 0; ls < 32; ls++) {
            float xv = Xt[ls][p] * wv[ls];
            const float* br = &Bt[ls][ng * 32];
#pragma unroll
            for (int j = 0; j < 32; j += 4) {
                float4 b4 = *(const float4*)(br + j);
                acc[j + 0] = fmaf(xv, b4.x, acc[j + 0]);
                acc[j + 1] = fmaf(xv, b4.y, acc[j + 1]);
                acc[j + 2] = fmaf(xv, b4.z, acc[j + 2]);
                acc[j + 3] = fmaf(xv, b4.w, acc[j + 3]);
            }
        }
    }
    float* dst = &g_states[(((size_t)c * NH + h) * DH + p) * DS + ng * 32];
#pragma unroll
    for (int j = 0; j < 32; j += 4)
        *(float4*)(dst + j) = make_float4(acc[j], acc[j + 1], acc[j + 2], acc[j + 3]);
}

// ======================= inter-chunk carry scan =======================
__global__ void carry_kernel() {
    int h = blockIdx.x;
    int tid = threadIdx.x;
    float carry[32];
#pragma unroll
    for (int j = 0; j < 32; j++) carry[j] = 0.f;
    for (int c = 0; c < NCH; c++) {
        float dec = __expf(g_acum[(size_t)(c * CHUNK + CHUNK - 1) * NH + h]);
        size_t off = ((size_t)c * NH + h) * DH * DS + (size_t)tid * 32;
#pragma unroll
        for (int j = 0; j < 32; j += 4) {
            float4 st = *(const float4*)&g_states[off + j];
            *(float4*)&g_prev[off + j] = make_float4(carry[j], carry[j + 1], carry[j + 2], carry[j + 3]);
            carry[j + 0] = fmaf(carry[j + 0], dec, st.x);
            carry[j + 1] = fmaf(carry[j + 1], dec, st.y);
            carry[j + 2] = fmaf(carry[j + 2], dec, st.z);
            carry[j + 3] = fmaf(carry[j + 3], dec, st.w);
        }
    }
}

// ======================= Y = intra + inter + D skip =======================
__global__ __launch_bounds__(256) void y_kernel(const float* __restrict__ Dp) {
    const int tt = blockIdx.x;
    const int h  = blockIdx.y;
    const int c  = blockIdx.z;
    __shared__ float sM[64][68];
    __shared__ float sX[64][68];
    __shared__ float sAcT[64], sAcS[64], sDt[64], sEt[64], sEs[64];
    const int tid = threadIdx.x;
    const int tx = tid & 15, ty = tid >> 4;

    if (tid < 64)
        sAcT[tid] = g_acum[(size_t)(c * CHUNK + tt * 64 + tid) * NH + h];

    float acc[4][4] = {};

    for (int n0 = 0; n0 < DS; n0 += 32) {
        __syncthreads();
        for (int e = tid; e < 64 * 32; e += 256) {
            int r = e >> 5, kk = e & 31;
            sM[kk][r] = g_conv[(size_t)(c * CHUNK + tt * 64 + r) * CONV_DIM + INTER + DS + n0 + kk];
            sX[kk][r] = g_prev[(((size_t)c * NH + h) * DH + r) * DS + n0 + kk];
        }
        __syncthreads();
#pragma unroll
        for (int k = 0; k < 32; k++) {
            float4 a = *(const float4*)&sM[k][ty * 4];
            float4 b = *(const float4*)&sX[k][tx * 4];
            float av[4] = {a.x, a.y, a.z, a.w};
            float bv[4] = {b.x, b.y, b.z, b.w};
#pragma unroll
            for (int i = 0; i < 4; i++)
#pragma unroll
                for (int j = 0; j < 4; j++)
                    acc[i][j] = fmaf(av[i], bv[j], acc[i][j]);
        }
    }
#pragma unroll
    for (int i = 0; i < 4; i++) {
        float e = __expf(sAcT[ty * 4 + i]);
#pragma unroll
        for (int j = 0; j < 4; j++) acc[i][j] *= e;
    }

    for (int st = 0; st <= tt; st++) {
        __syncthreads();
        if (tid < 64) {
            sAcS[tid] = g_acum[(size_t)(c * CHUNK + st * 64 + tid) * NH + h];
            sDt[tid]  = g_dt  [(size_t)(c * CHUNK + st * 64 + tid) * NH + h];
        }
        __syncthreads();
        if (st < tt && tid < 64) {
            float ref = sAcS[63];
            sEt[tid] = __expf(sAcT[tid] - ref);
            sEs[tid] = __expf(ref - sAcS[tid]) * sDt[tid];
        }
        __syncthreads();
        for (int e = tid; e < 64 * 64; e += 256) {
            int t = e >> 6, s = e & 63;
            float cb = g_cb[(size_t)c * CHUNK * CHUNK + (size_t)(tt * 64 + t) * CHUNK + st * 64 + s];
            float m;
            if (st < tt) m = cb * sEt[t] * sEs[s];
            else         m = (s <= t) ? cb * __expf(sAcT[t] - sAcS[s]) * sDt[s] : 0.f;
            sM[s][t] = m;
        }
        for (int e = tid; e < 64 * 64; e += 256) {
            int s = e >> 6, pp = e & 63;
            sX[s][pp] = g_conv[(size_t)(c * CHUNK + st * 64 + s) * CONV_DIM + h * DH + pp];
        }
        __syncthreads();
#pragma unroll 8
        for (int s = 0; s < 64; s++) {
            float4 a = *(const float4*)&sM[s][ty * 4];
            float4 b = *(const float4*)&sX[s][tx * 4];
            float av[4] = {a.x, a.y, a.z, a.w};
            float bv[4] = {b.x, b.y, b.z, b.w};
#pragma unroll
            for (int i = 0; i < 4; i++)
#pragma unroll
                for (int j = 0; j < 4; j++)
                    acc[i][j] = fmaf(av[i], bv[j], acc[i][j]);
        }
    }

    float dv = Dp[h];
#pragma unroll
    for (int i = 0; i < 4; i++)
#pragma unroll
        for (int j = 0; j < 4; j++)
            acc[i][j] = fmaf(dv, sX[ty * 4 + i][tx * 4 + j], acc[i][j]);

#pragma unroll
    for (int i = 0; i < 4; i++)
        *(float4*)&g_y[(size_t)(c * CHUNK + tt * 64 + ty * 4 + i) * INTER + h * DH + tx * 4] =
            make_float4(acc[i][0], acc[i][1], acc[i][2], acc[i][3]);
}

// ======================= gated RMSNorm -> fp16 output =======================
__global__ __launch_bounds__(256) void norm_kernel(const float* __restrict__ norm_w) {
    int s = blockIdx.x;
    int tid = threadIdx.x;
    float v[16];
    float ss = 0.f;
#pragma unroll
    for (int q = 0; q < 4; q++) {
        int i4 = tid + q * 256;
        float4 y4 = *(const float4*)&g_y[(size_t)s * INTER + (size_t)i4 * 4];
        float4 g4 = *(const float4*)&g_proj[(size_t)s * PROJ_DIM + (size_t)i4 * 4];
        float t0 = y4.x * (g4.x / (1.f + __expf(-g4.x)));
        float t1 = y4.y * (g4.y / (1.f + __expf(-g4.y)));
        float t2 = y4.z * (g4.z / (1.f + __expf(-g4.z)));
        float t3 = y4.w * (g4.w / (1.f + __expf(-g4.w)));
        v[q * 4 + 0] = t0; v[q * 4 + 1] = t1; v[q * 4 + 2] = t2; v[q * 4 + 3] = t3;
        ss += t0 * t0 + t1 * t1 + t2 * t2 + t3 * t3;
    }
#pragma unroll
    for (int o = 16; o > 0; o >>= 1) ss += __shfl_xor_sync(0xffffffffu, ss, o);
    __shared__ float red[8];
    if ((tid & 31) == 0) red[tid >> 5] = ss;
    __syncthreads();
    float tot = red[0] + red[1] + red[2] + red[3] + red[4] + red[5] + red[6] + red[7];
    float scale = rsqrtf(tot * (1.f / INTER) + 1e-5f);
#pragma unroll
    for (int q = 0; q < 4; q++) {
        int i4 = tid + q * 256;
        float4 w4 = *(const float4*)&norm_w[(size_t)i4 * 4];
        float o0 = v[q * 4 + 0] * scale * w4.x;
        float o1 = v[q * 4 + 1] * scale * w4.y;
        float o2 = v[q * 4 + 2] * scale * w4.z;
        float o3 = v[q * 4 + 3] * scale * w4.w;
        size_t base = (size_t)s * INTER + (size_t)i4 * 4;
        *(__half2*)(g_yh + base)     = __half2(__float2half_rn(o0), __float2half_rn(o1));
        *(__half2*)(g_yh + base + 2) = __half2(__float2half_rn(o2), __float2half_rn(o3));
    }
}

// ======================= launch =======================
extern "C" void kernel_launch(void* const* d_in, const int* in_sizes, int n_in,
                              void* d_out, int out_size) {
    (void)in_sizes; (void)n_in; (void)out_size;
    const float* x       = (const float*)d_in[0];
    const float* W_in    = (const float*)d_in[1];
    const float* conv_w  = (const float*)d_in[2];
    const float* conv_b  = (const float*)d_in[3];
    const float* dt_bias = (const float*)d_in[4];
    const float* A_log   = (const float*)d_in[5];
    const float* Dp      = (const float*)d_in[6];
    const float* norm_w  = (const float*)d_in[7];
    const float* W_out   = (const float*)d_in[8];
    float* out = (float*)d_out;

    // stage = A(10240) + B(NT*80): NT=256 -> 30720; NT=64 -> 15360. 4 stages.
    const int SM256 = 4 * (128 * PITCH * 2 + 256 * PITCH * 2); // 122880
    const int SM64  = 4 * (128 * PITCH * 2 + 64 * PITCH * 2);  // 61440
    cudaFuncSetAttribute(gemm_mma_kernel<HIDDEN, PROJ_DIM, 256>,
                         cudaFuncAttributeMaxDynamicSharedMemorySize, SM256);
    cudaFuncSetAttribute(gemm_mma_kernel<HIDDEN, PROJ_DIM, 64>,
                         cudaFuncAttributeMaxDynamicSharedMemorySize, SM64);
    cudaFuncSetAttribute(gemm_mma_kernel<INTER, HIDDEN, 256>,
                         cudaFuncAttributeMaxDynamicSharedMemorySize, SM256);

    __half *xh, *wih, *yh, *woh;
    cudaGetSymbolAddress((void**)&xh,  g_xh);
    cudaGetSymbolAddress((void**)&wih, g_wih);
    cudaGetSymbolAddress((void**)&yh,  g_yh);
    cudaGetSymbolAddress((void**)&woh, g_woh);
    float* proj; cudaGetSymbolAddress((void**)&proj, g_proj);

    split1_kernel<<<(SEQ * HIDDEN / 4 + 255) / 256, 256>>>(x, xh, SEQ * HIDDEN);
    split1_kernel<<<(PROJ_DIM * HIDDEN / 4 + 255) / 256, 256>>>(W_in, wih, PROJ_DIM * HIDDEN);
    split1_kernel<<<(HIDDEN * INTER / 4 + 255) / 256, 256>>>(W_out, woh, HIDDEN * INTER);

    gemm_mma_kernel<HIDDEN, PROJ_DIM, 256><<<dim3(33, 16), 256, SM256>>>(xh, wih, proj, 0);
    gemm_mma_kernel<HIDDEN, PROJ_DIM, 64><<<dim3(1, 16), 256, SM64>>>(xh, wih, proj, 8448);

    conv_silu_kernel<<<(SEQ * CONV_DIM + 255) / 256, 256>>>(conv_w, conv_b);
    dt_kernel<<<(SEQ * NH) / 256, 256>>>(dt_bias);
    acum_kernel<<<64, 256>>>(A_log);
    cb_kernel<<<dim3(4, 4, NCH), 256>>>();
    states_kernel<<<dim3(NH, NCH), 256>>>();
    carry_kernel<<<NH, 256>>>();
    y_kernel<<<dim3(4, NH, NCH), 256>>>(Dp);
    norm_kernel<<<SEQ, 256>>>(norm_w);

    gemm_mma_kernel<INTER, HIDDEN, 256><<<dim3(8, 16), 256, SM256>>>(yh, woh, out, 0);
}

// round 17
// speedup vs baseline: 1.0292x; 1.0292x over previous
#include <cuda_runtime.h>
#include <cuda_fp16.h>
#include <stdint.h>
#include <math.h>

#define SEQ 2048
#define HIDDEN 2048
#define INTER 4096
#define NH 64
#define DH 64
#define DS 128
#define CHUNK 256
#define NCH 8
#define CONV_DIM 4352
#define PROJ_DIM 8512

// -------- scratch (device globals; no allocation allowed) --------
__device__ float g_proj[SEQ * PROJ_DIM];
__device__ float g_conv[SEQ * CONV_DIM];
__device__ float g_dt[SEQ * NH];
__device__ float g_acum[SEQ * NH];
__device__ float g_cb[NCH * CHUNK * CHUNK];
__device__ float g_states[NCH * NH * DH * DS];
__device__ float g_prev[NCH * NH * DH * DS];
__device__ float g_y[SEQ * INTER];

// fp16 operands for tensor-core GEMMs (single product: hi only)
__device__ __half g_xh[SEQ * HIDDEN];
__device__ __half g_wih[PROJ_DIM * HIDDEN];
__device__ __half g_yh[SEQ * INTER];
__device__ __half g_woh[HIDDEN * INTER];

// ======================= helpers =======================
__device__ __forceinline__ uint32_t smem_u32(const void* p) {
    uint32_t a;
    asm("{ .reg .u64 t; cvta.to.shared.u64 t, %1; cvt.u32.u64 %0, t; }" : "=r"(a) : "l"(p));
    return a;
}

#define LDSM4(r, a) \
    asm volatile("ldmatrix.sync.aligned.m8n8.x4.shared.b16 {%0,%1,%2,%3}, [%4];" \
        : "=r"((r)[0]), "=r"((r)[1]), "=r"((r)[2]), "=r"((r)[3]) : "r"(a))

#define MMA16816(c, a, b0, b1) \
    asm volatile("mma.sync.aligned.m16n8k16.row.col.f32.f16.f16.f32 " \
        "{%0,%1,%2,%3}, {%4,%5,%6,%7}, {%8,%9}, {%0,%1,%2,%3};" \
        : "+f"((c)[0]), "+f"((c)[1]), "+f"((c)[2]), "+f"((c)[3]) \
        : "r"((a)[0]), "r"((a)[1]), "r"((a)[2]), "r"((a)[3]), "r"(b0), "r"(b1))

__device__ __forceinline__ void cp16(uint32_t dst, const void* src) {
    unsigned long long g = (unsigned long long)__cvta_generic_to_global(src);
    asm volatile("cp.async.cg.shared.global [%0], [%1], 16;" :: "r"(dst), "l"(g));
}

// ======================= fp32 -> fp16 =======================
__global__ void split1_kernel(const float* __restrict__ in, __half* __restrict__ hi, int n) {
    int i = (blockIdx.x * blockDim.x + threadIdx.x) * 4;
    if (i >= n) return;
    float4 v = *(const float4*)(in + i);
    *(__half2*)(hi + i)     = __half2(__float2half_rn(v.x), __float2half_rn(v.y));
    *(__half2*)(hi + i + 2) = __half2(__float2half_rn(v.z), __float2half_rn(v.w));
}

// ======================= mma.sync GEMM: C[M, slice] = A[M,K] * B[N,K]^T =======================
// Single fp16 product (A hi x B hi). CTA 128 x NT (256 main / 64 tail),
// 512 threads (warps 4x4, warp tile 32x64), 4-stage cp.async, pitch 40 half (80B).
#define PITCH 40

template<int K, int NT>
__device__ __forceinline__ void issue_tile(uint32_t st, int t, int bm, int bn,
        const __half* __restrict__ Ah, const __half* __restrict__ Bh, int tid) {
    constexpr int ABYTES = 128 * PITCH * 2;
    const int kt = t * 32;
    {   // A: 128 rows x 4 chunks = 512 chunks (one per thread)
        int r = tid >> 2, q = tid & 3;
        size_t src = (size_t)(bm + r) * K + kt + q * 8;
        cp16(st + (uint32_t)(r * PITCH + q * 8) * 2, Ah + src);
    }
    constexpr int BCH = NT * 4;
#pragma unroll
    for (int i = 0; i < (BCH + 511) / 512; i++) {
        int cid = tid + i * 512;
        if ((BCH % 512 == 0) || cid < BCH) {
            int r = cid >> 2, q = cid & 3;
            size_t src = (size_t)(bn + r) * K + kt + q * 8;
            cp16(st + ABYTES + (uint32_t)(r * PITCH + q * 8) * 2, Bh + src);
        }
    }
}

template<int K, int NS, int NT>
__global__ __launch_bounds__(512, 1) void gemm_mma_kernel(
        const __half* __restrict__ Ah, const __half* __restrict__ Bh,
        float* __restrict__ C, int n0) {
    extern __shared__ char smem[];
    constexpr int ABYTES = 128 * PITCH * 2;
    constexpr int BBYTES = NT * PITCH * 2;
    constexpr int STAGE = ABYTES + BBYTES;
    constexpr int T = K / 32;
    constexpr int WNF = NT / 32;        // n8 frags per warp (4 n-warps)
    constexpr int WSPAN = NT / 4;       // cols per warp

    const int tid = threadIdx.x;
    const int lane = tid & 31, wid = tid >> 5;
    const int wm = wid & 3, wn = wid >> 2;
    const int bm = blockIdx.y * 128;
    const int bn = n0 + blockIdx.x * NT;
    const uint32_t sb = smem_u32(smem);

    float acc[2][WNF][4];
#pragma unroll
    for (int i = 0; i < 2; i++)
#pragma unroll
        for (int j = 0; j < WNF; j++)
#pragma unroll
            for (int q = 0; q < 4; q++) acc[i][j][q] = 0.f;

    issue_tile<K, NT>(sb,             0, bm, bn, Ah, Bh, tid);
    asm volatile("cp.async.commit_group;" ::: "memory");
    issue_tile<K, NT>(sb + STAGE,     1, bm, bn, Ah, Bh, tid);
    asm volatile("cp.async.commit_group;" ::: "memory");
    issue_tile<K, NT>(sb + 2 * STAGE, 2, bm, bn, Ah, Bh, tid);
    asm volatile("cp.async.commit_group;" ::: "memory");

    const int lrow = lane & 15;
    const int lcol = (lane >> 4) * 8;
    const uint32_t aoff = (uint32_t)((wm * 32 + lrow) * PITCH + lcol) * 2;
    const uint32_t boff = ABYTES + (uint32_t)((wn * WSPAN + lrow) * PITCH + lcol) * 2;

    for (int t = 0; t < T; t++) {
        asm volatile("cp.async.wait_group 2;" ::: "memory");
        __syncthreads();
        const uint32_t stg = sb + (uint32_t)(t & 3) * STAGE;
#pragma unroll
        for (int kk = 0; kk < 32; kk += 16) {
            uint32_t ah[2][4];
#pragma unroll
            for (int fm = 0; fm < 2; fm++)
                LDSM4(ah[fm], stg + aoff + (uint32_t)(fm * 16 * PITCH + kk) * 2);
#pragma unroll
            for (int g = 0; g < WNF / 2; g++) {
                uint32_t bd = stg + boff + (uint32_t)(g * 16 * PITCH + kk) * 2;
                uint32_t rh[4];
                LDSM4(rh, bd);
#pragma unroll
                for (int fm = 0; fm < 2; fm++) {
                    MMA16816(acc[fm][2 * g],     ah[fm], rh[0], rh[2]);
                    MMA16816(acc[fm][2 * g + 1], ah[fm], rh[1], rh[3]);
                }
            }
        }
        if (t + 3 < T)
            issue_tile<K, NT>(sb + (uint32_t)((t + 3) & 3) * STAGE, t + 3, bm, bn, Ah, Bh, tid);
        asm volatile("cp.async.commit_group;" ::: "memory");
    }

    const int crow = lane >> 2, ccol = (lane & 3) * 2;
#pragma unroll
    for (int fm = 0; fm < 2; fm++)
#pragma unroll
        for (int fn = 0; fn < WNF; fn++) {
            int m = bm + wm * 32 + fm * 16 + crow;
            int n = bn + wn * WSPAN + fn * 8 + ccol;
            *(float2*)&C[(size_t)m * NS + n]       = make_float2(acc[fm][fn][0], acc[fm][fn][1]);
            *(float2*)&C[(size_t)(m + 8) * NS + n] = make_float2(acc[fm][fn][2], acc[fm][fn][3]);
        }
}

// ======================= depthwise causal conv (K=4) + SiLU =======================
__global__ void conv_silu_kernel(const float* __restrict__ conv_w,
                                 const float* __restrict__ conv_b) {
    int idx = blockIdx.x * blockDim.x + threadIdx.x;
    if (idx >= SEQ * CONV_DIM) return;
    int s = idx / CONV_DIM;
    int c = idx - s * CONV_DIM;
    float w0 = conv_w[c * 4 + 0], w1 = conv_w[c * 4 + 1];
    float w2 = conv_w[c * 4 + 2], w3 = conv_w[c * 4 + 3];
    const float* col = g_proj + INTER + c;
    float acc = conv_b[c];
    if (s >= 3) acc = fmaf(col[(size_t)(s - 3) * PROJ_DIM], w0, acc);
    if (s >= 2) acc = fmaf(col[(size_t)(s - 2) * PROJ_DIM], w1, acc);
    if (s >= 1) acc = fmaf(col[(size_t)(s - 1) * PROJ_DIM], w2, acc);
    acc = fmaf(col[(size_t)s * PROJ_DIM], w3, acc);
    float sig = 1.f / (1.f + __expf(-acc));
    g_conv[idx] = acc * sig;
}

// ======================= fused dt softplus + per-chunk cumsum scan, warp per (c,h) =======================
__global__ void acum_kernel(const float* __restrict__ A_log,
                            const float* __restrict__ dt_bias) {
    int wg = blockIdx.x * 8 + (threadIdx.x >> 5);  // 0..511 -> (c,h)
    int lane = threadIdx.x & 31;
    int c = wg >> 6, h = wg & 63;
    float A = -__expf(A_log[h]);
    float bias = dt_bias[h];
    const float* rawp = g_proj + (size_t)(c * CHUNK) * PROJ_DIM + (INTER + CONV_DIM) + h;
    float dtv[8], v[8];
    float run = 0.f;
#pragma unroll
    for (int j = 0; j < 8; j++) {
        float r = rawp[(size_t)(lane * 8 + j) * PROJ_DIM] + bias;
        float dt = (r > 20.f) ? r : log1pf(__expf(r));
        dtv[j] = dt;
        v[j] = dt * A;
        run += v[j];
    }
    float s = run;
#pragma unroll
    for (int o = 1; o < 32; o <<= 1) {
        float t = __shfl_up_sync(0xffffffffu, s, o);
        if (lane >= o) s += t;
    }
    float acc = s - run;   // exclusive prefix
    float* acp = g_acum + (size_t)(c * CHUNK) * NH + h;
    float* dtp = g_dt + (size_t)(c * CHUNK) * NH + h;
#pragma unroll
    for (int j = 0; j < 8; j++) {
        acc += v[j];
        acp[(size_t)(lane * 8 + j) * NH] = acc;
        dtp[(size_t)(lane * 8 + j) * NH] = dtv[j];
    }
}

// ======================= CB[c][t][s] = C_t . B_s (shared over heads), s<=t tiles only =======================
__global__ __launch_bounds__(256) void cb_kernel() {
    int st = blockIdx.x, tt = blockIdx.y, c = blockIdx.z;
    if (st > tt) return;
    __shared__ float Cs[32][68];
    __shared__ float Bs2[32][68];
    const int tid = threadIdx.x;
    const int tx = tid & 15, ty = tid >> 4;
    float acc[4][4] = {};
    for (int n0 = 0; n0 < DS; n0 += 32) {
        __syncthreads();
        for (int e = tid; e < 64 * 32; e += 256) {
            int r = e >> 5, kk = e & 31;
            Cs[kk][r]  = g_conv[(size_t)(c * CHUNK + tt * 64 + r) * CONV_DIM + INTER + DS + n0 + kk];
            Bs2[kk][r] = g_conv[(size_t)(c * CHUNK + st * 64 + r) * CONV_DIM + INTER + n0 + kk];
        }
        __syncthreads();
#pragma unroll
        for (int k = 0; k < 32; k++) {
            float4 a = *(const float4*)&Cs[k][ty * 4];
            float4 b = *(const float4*)&Bs2[k][tx * 4];
            float av[4] = {a.x, a.y, a.z, a.w};
            float bv[4] = {b.x, b.y, b.z, b.w};
#pragma unroll
            for (int i = 0; i < 4; i++)
#pragma unroll
                for (int j = 0; j < 4; j++)
                    acc[i][j] = fmaf(av[i], bv[j], acc[i][j]);
        }
    }
#pragma unroll
    for (int i = 0; i < 4; i++)
        *(float4*)&g_cb[(size_t)c * CHUNK * CHUNK + (size_t)(tt * 64 + ty * 4 + i) * CHUNK + st * 64 + tx * 4] =
            make_float4(acc[i][0], acc[i][1], acc[i][2], acc[i][3]);
}

// ======================= chunk end states: states[c][h][p][n] =======================
__global__ __launch_bounds__(256) void states_kernel() {
    int h = blockIdx.x, c = blockIdx.y;
    __shared__ float Bt[32][DS];
    __shared__ float Xt[32][DH];
    __shared__ float wv[32];
    const int tid = threadIdx.x;
    const int p = tid >> 2, ng = tid & 3;
    float acc[32];
#pragma unroll
    for (int j = 0; j < 32; j++) acc[j] = 0.f;
    float Aend = g_acum[(size_t)(c * CHUNK + CHUNK - 1) * NH + h];
    for (int lt = 0; lt < 8; lt++) {
        __syncthreads();
        for (int e = tid; e < 32 * DS; e += 256) {
            int r = e >> 7, n = e & 127;
            Bt[r][n] = g_conv[(size_t)(c * CHUNK + lt * 32 + r) * CONV_DIM + INTER + n];
        }
        for (int e = tid; e < 32 * DH; e += 256) {
            int r = e >> 6, pp = e & 63;
            Xt[r][pp] = g_conv[(size_t)(c * CHUNK + lt * 32 + r) * CONV_DIM + h * DH + pp];
        }
        if (tid < 32) {
            int l = lt * 32 + tid;
            float ac = g_acum[(size_t)(c * CHUNK + l) * NH + h];
            wv[tid] = __expf(Aend - ac) * g_dt[(size_t)(c * CHUNK + l) * NH + h];
        }
        __syncthreads();
#pragma unroll 4
        for (int ls = 0; ls < 32; ls++) {
            float xv = Xt[ls][p] * wv[ls];
            const float* br = &Bt[ls][ng * 32];
#pragma unroll
            for (int j = 0; j < 32; j += 4) {
                float4 b4 = *(const float4*)(br + j);
                acc[j + 0] = fmaf(xv, b4.x, acc[j + 0]);
                acc[j + 1] = fmaf(xv, b4.y, acc[j + 1]);
                acc[j + 2] = fmaf(xv, b4.z, acc[j + 2]);
                acc[j + 3] = fmaf(xv, b4.w, acc[j + 3]);
            }
        }
    }
    float* dst = &g_states[(((size_t)c * NH + h) * DH + p) * DS + ng * 32];
#pragma unroll
    for (int j = 0; j < 32; j += 4)
        *(float4*)(dst + j) = make_float4(acc[j], acc[j + 1], acc[j + 2], acc[j + 3]);
}

// ======================= inter-chunk carry scan =======================
__global__ void carry_kernel() {
    int h = blockIdx.x;
    int tid = threadIdx.x;
    float carry[32];
#pragma unroll
    for (int j = 0; j < 32; j++) carry[j] = 0.f;
    for (int c = 0; c < NCH; c++) {
        float dec = __expf(g_acum[(size_t)(c * CHUNK + CHUNK - 1) * NH + h]);
        size_t off = ((size_t)c * NH + h) * DH * DS + (size_t)tid * 32;
#pragma unroll
        for (int j = 0; j < 32; j += 4) {
            float4 st = *(const float4*)&g_states[off + j];
            *(float4*)&g_prev[off + j] = make_float4(carry[j], carry[j + 1], carry[j + 2], carry[j + 3]);
            carry[j + 0] = fmaf(carry[j + 0], dec, st.x);
            carry[j + 1] = fmaf(carry[j + 1], dec, st.y);
            carry[j + 2] = fmaf(carry[j + 2], dec, st.z);
            carry[j + 3] = fmaf(carry[j + 3], dec, st.w);
        }
    }
}

// ======================= Y = intra + inter + D skip =======================
__global__ __launch_bounds__(256) void y_kernel(const float* __restrict__ Dp) {
    const int tt = blockIdx.x;
    const int h  = blockIdx.y;
    const int c  = blockIdx.z;
    __shared__ float sM[64][68];
    __shared__ float sX[64][68];
    __shared__ float sAcT[64], sAcS[64], sDt[64], sEt[64], sEs[64];
    const int tid = threadIdx.x;
    const int tx = tid & 15, ty = tid >> 4;

    if (tid < 64)
        sAcT[tid] = g_acum[(size_t)(c * CHUNK + tt * 64 + tid) * NH + h];

    float acc[4][4] = {};

    for (int n0 = 0; n0 < DS; n0 += 32) {
        __syncthreads();
        for (int e = tid; e < 64 * 32; e += 256) {
            int r = e >> 5, kk = e & 31;
            sM[kk][r] = g_conv[(size_t)(c * CHUNK + tt * 64 + r) * CONV_DIM + INTER + DS + n0 + kk];
            sX[kk][r] = g_prev[(((size_t)c * NH + h) * DH + r) * DS + n0 + kk];
        }
        __syncthreads();
#pragma unroll
        for (int k = 0; k < 32; k++) {
            float4 a = *(const float4*)&sM[k][ty * 4];
            float4 b = *(const float4*)&sX[k][tx * 4];
            float av[4] = {a.x, a.y, a.z, a.w};
            float bv[4] = {b.x, b.y, b.z, b.w};
#pragma unroll
            for (int i = 0; i < 4; i++)
#pragma unroll
                for (int j = 0; j < 4; j++)
                    acc[i][j] = fmaf(av[i], bv[j], acc[i][j]);
        }
    }
#pragma unroll
    for (int i = 0; i < 4; i++) {
        float e = __expf(sAcT[ty * 4 + i]);
#pragma unroll
        for (int j = 0; j < 4; j++) acc[i][j] *= e;
    }

    for (int st = 0; st <= tt; st++) {
        __syncthreads();
        if (tid < 64) {
            sAcS[tid] = g_acum[(size_t)(c * CHUNK + st * 64 + tid) * NH + h];
            sDt[tid]  = g_dt  [(size_t)(c * CHUNK + st * 64 + tid) * NH + h];
        }
        __syncthreads();
        if (st < tt && tid < 64) {
            float ref = sAcS[63];
            sEt[tid] = __expf(sAcT[tid] - ref);
            sEs[tid] = __expf(ref - sAcS[tid]) * sDt[tid];
        }
        __syncthreads();
        for (int e = tid; e < 64 * 64; e += 256) {
            int t = e >> 6, s = e & 63;
            float cb = g_cb[(size_t)c * CHUNK * CHUNK + (size_t)(tt * 64 + t) * CHUNK + st * 64 + s];
            float m;
            if (st < tt) m = cb * sEt[t] * sEs[s];
            else         m = (s <= t) ? cb * __expf(sAcT[t] - sAcS[s]) * sDt[s] : 0.f;
            sM[s][t] = m;
        }
        for (int e = tid; e < 64 * 64; e += 256) {
            int s = e >> 6, pp = e & 63;
            sX[s][pp] = g_conv[(size_t)(c * CHUNK + st * 64 + s) * CONV_DIM + h * DH + pp];
        }
        __syncthreads();
#pragma unroll 8
        for (int s = 0; s < 64; s++) {
            float4 a = *(const float4*)&sM[s][ty * 4];
            float4 b = *(const float4*)&sX[s][tx * 4];
            float av[4] = {a.x, a.y, a.z, a.w};
            float bv[4] = {b.x, b.y, b.z, b.w};
#pragma unroll
            for (int i = 0; i < 4; i++)
#pragma unroll
                for (int j = 0; j < 4; j++)
                    acc[i][j] = fmaf(av[i], bv[j], acc[i][j]);
        }
    }

    float dv = Dp[h];
#pragma unroll
    for (int i = 0; i < 4; i++)
#pragma unroll
        for (int j = 0; j < 4; j++)
            acc[i][j] = fmaf(dv, sX[ty * 4 + i][tx * 4 + j], acc[i][j]);

#pragma unroll
    for (int i = 0; i < 4; i++)
        *(float4*)&g_y[(size_t)(c * CHUNK + tt * 64 + ty * 4 + i) * INTER + h * DH + tx * 4] =
            make_float4(acc[i][0], acc[i][1], acc[i][2], acc[i][3]);
}

// ======================= gated RMSNorm -> fp16 output =======================
__global__ __launch_bounds__(256) void norm_kernel(const float* __restrict__ norm_w) {
    int s = blockIdx.x;
    int tid = threadIdx.x;
    float v[16];
    float ss = 0.f;
#pragma unroll
    for (int q = 0; q < 4; q++) {
        int i4 = tid + q * 256;
        float4 y4 = *(const float4*)&g_y[(size_t)s * INTER + (size_t)i4 * 4];
        float4 g4 = *(const float4*)&g_proj[(size_t)s * PROJ_DIM + (size_t)i4 * 4];
        float t0 = y4.x * (g4.x / (1.f + __expf(-g4.x)));
        float t1 = y4.y * (g4.y / (1.f + __expf(-g4.y)));
        float t2 = y4.z * (g4.z / (1.f + __expf(-g4.z)));
        float t3 = y4.w * (g4.w / (1.f + __expf(-g4.w)));
        v[q * 4 + 0] = t0; v[q * 4 + 1] = t1; v[q * 4 + 2] = t2; v[q * 4 + 3] = t3;
        ss += t0 * t0 + t1 * t1 + t2 * t2 + t3 * t3;
    }
#pragma unroll
    for (int o = 16; o > 0; o >>= 1) ss += __shfl_xor_sync(0xffffffffu, ss, o);
    __shared__ float red[8];
    if ((tid & 31) == 0) red[tid >> 5] = ss;
    __syncthreads();
    float tot = red[0] + red[1] + red[2] + red[3] + red[4] + red[5] + red[6] + red[7];
    float scale = rsqrtf(tot * (1.f / INTER) + 1e-5f);
#pragma unroll
    for (int q = 0; q < 4; q++) {
        int i4 = tid + q * 256;
        float4 w4 = *(const float4*)&norm_w[(size_t)i4 * 4];
        float o0 = v[q * 4 + 0] * scale * w4.x;
        float o1 = v[q * 4 + 1] * scale * w4.y;
        float o2 = v[q * 4 + 2] * scale * w4.z;
        float o3 = v[q * 4 + 3] * scale * w4.w;
        size_t base = (size_t)s * INTER + (size_t)i4 * 4;
        *(__half2*)(g_yh + base)     = __half2(__float2half_rn(o0), __float2half_rn(o1));
        *(__half2*)(g_yh + base + 2) = __half2(__float2half_rn(o2), __float2half_rn(o3));
    }
}

// ======================= launch =======================
extern "C" void kernel_launch(void* const* d_in, const int* in_sizes, int n_in,
                              void* d_out, int out_size) {
    (void)in_sizes; (void)n_in; (void)out_size;
    const float* x       = (const float*)d_in[0];
    const float* W_in    = (const float*)d_in[1];
    const float* conv_w  = (const float*)d_in[2];
    const float* conv_b  = (const float*)d_in[3];
    const float* dt_bias = (const float*)d_in[4];
    const float* A_log   = (const float*)d_in[5];
    const float* Dp      = (const float*)d_in[6];
    const float* norm_w  = (const float*)d_in[7];
    const float* W_out   = (const float*)d_in[8];
    float* out = (float*)d_out;

    // stage = A(10240) + B(NT*80): NT=256 -> 30720; NT=64 -> 15360. 4 stages.
    const int SM256 = 4 * (128 * PITCH * 2 + 256 * PITCH * 2); // 122880
    const int SM64  = 4 * (128 * PITCH * 2 + 64 * PITCH * 2);  // 61440
    cudaFuncSetAttribute(gemm_mma_kernel<HIDDEN, PROJ_DIM, 256>,
                         cudaFuncAttributeMaxDynamicSharedMemorySize, SM256);
    cudaFuncSetAttribute(gemm_mma_kernel<HIDDEN, PROJ_DIM, 64>,
                         cudaFuncAttributeMaxDynamicSharedMemorySize, SM64);
    cudaFuncSetAttribute(gemm_mma_kernel<INTER, HIDDEN, 256>,
                         cudaFuncAttributeMaxDynamicSharedMemorySize, SM256);

    __half *xh, *wih, *yh, *woh;
    cudaGetSymbolAddress((void**)&xh,  g_xh);
    cudaGetSymbolAddress((void**)&wih, g_wih);
    cudaGetSymbolAddress((void**)&yh,  g_yh);
    cudaGetSymbolAddress((void**)&woh, g_woh);
    float* proj; cudaGetSymbolAddress((void**)&proj, g_proj);

    split1_kernel<<<(SEQ * HIDDEN / 4 + 255) / 256, 256>>>(x, xh, SEQ * HIDDEN);
    split1_kernel<<<(PROJ_DIM * HIDDEN / 4 + 255) / 256, 256>>>(W_in, wih, PROJ_DIM * HIDDEN);
    split1_kernel<<<(HIDDEN * INTER / 4 + 255) / 256, 256>>>(W_out, woh, HIDDEN * INTER);

    gemm_mma_kernel<HIDDEN, PROJ_DIM, 256><<<dim3(33, 16), 512, SM256>>>(xh, wih, proj, 0);
    gemm_mma_kernel<HIDDEN, PROJ_DIM, 64><<<dim3(1, 16), 512, SM64>>>(xh, wih, proj, 8448);

    conv_silu_kernel<<<(SEQ * CONV_DIM + 255) / 256, 256>>>(conv_w, conv_b);
    acum_kernel<<<64, 256>>>(A_log, dt_bias);
    cb_kernel<<<dim3(4, 4, NCH), 256>>>();
    states_kernel<<<dim3(NH, NCH), 256>>>();
    carry_kernel<<<NH, 256>>>();
    y_kernel<<<dim3(4, NH, NCH), 256>>>(Dp);
    norm_kernel<<<SEQ, 256>>>(norm_w);

    gemm_mma_kernel<INTER, HIDDEN, 256><<<dim3(8, 16), 512, SM256>>>(yh, woh, out, 0);
}